// round 13
// baseline (speedup 1.0000x reference)
#include <cuda_runtime.h>
#include <cuda_fp16.h>
#include <mma.h>
#include <cstdint>

using namespace nvcuda;

// Problem constants (static shapes)
constexpr int HH   = 56;
constexpr int WWp  = 56;
constexpr int C    = 768;
constexpr int NH_  = 12;
constexpr int HD   = 64;
constexpr int WS_  = 14;
constexpr int N_   = 196;        // tokens per window
constexpr int NWIN = 256;        // 16 batch * 16 windows
constexpr int M_   = NWIN * N_;  // 50176 rows
constexpr int KQ   = 768;
constexpr int RLD  = 224;        // padded rpb row stride (halfs) = 7 tiles x 32

// -------- device scratch (allocation-free rule: __device__ globals) --------
__device__ __half g_xh[(size_t)M_ * C];          // window-ordered fp16 x
__device__ __half g_wqkv[2304 * 768];
__device__ __half g_wproj[768 * 768];
__device__ float  g_bqkv[2304];
__device__ __half g_q[(size_t)NWIN * NH_ * N_ * HD];
__device__ __half g_k[(size_t)NWIN * NH_ * N_ * HD];
__device__ __half g_v[(size_t)NWIN * NH_ * N_ * HD];
__device__ __half g_rpbh[(size_t)NH_ * N_ * RLD];  // half, tile-permuted cols (L2-resident)
__device__ __half g_ao[(size_t)M_ * C];          // attention output (proj input)

// ---------------- raw-PTX helpers (all sm_80-level; safe on compute_103) ----
__device__ __forceinline__ uint32_t smem_u32(const void* p) {
  uint32_t a;
  asm("{ .reg .u64 t; cvta.to.shared.u64 t, %1; cvt.u32.u64 %0, t; }" : "=r"(a) : "l"(p));
  return a;
}
__device__ __forceinline__ void cpa16(uint32_t dst, const void* src, bool valid) {
  int sz = valid ? 16 : 0;
  asm volatile("cp.async.cg.shared.global [%0], [%1], 16, %2;"
               :: "r"(dst), "l"(src), "r"(sz) : "memory");
}
__device__ __forceinline__ void ldx4(uint32_t* r, uint32_t a) {
  asm volatile("ldmatrix.sync.aligned.m8n8.x4.shared.b16 {%0,%1,%2,%3}, [%4];"
               : "=r"(r[0]), "=r"(r[1]), "=r"(r[2]), "=r"(r[3]) : "r"(a));
}
__device__ __forceinline__ void ldx4t(uint32_t* r, uint32_t a) {
  asm volatile("ldmatrix.sync.aligned.m8n8.x4.trans.shared.b16 {%0,%1,%2,%3}, [%4];"
               : "=r"(r[0]), "=r"(r[1]), "=r"(r[2]), "=r"(r[3]) : "r"(a));
}
__device__ __forceinline__ void ldx2(uint32_t* r, uint32_t a) {
  asm volatile("ldmatrix.sync.aligned.m8n8.x2.shared.b16 {%0,%1}, [%2];"
               : "=r"(r[0]), "=r"(r[1]) : "r"(a));
}
__device__ __forceinline__ void mma16816(float* d, const uint32_t* a, const uint32_t* b) {
  asm volatile("mma.sync.aligned.m16n8k16.row.col.f32.f16.f16.f32 "
               "{%0,%1,%2,%3}, {%4,%5,%6,%7}, {%8,%9}, {%0,%1,%2,%3};"
               : "+f"(d[0]), "+f"(d[1]), "+f"(d[2]), "+f"(d[3])
               : "r"(a[0]), "r"(a[1]), "r"(a[2]), "r"(a[3]), "r"(b[0]), "r"(b[1]));
}
__device__ __forceinline__ uint32_t packh2(float lo, float hi) {
  uint32_t p;
  asm("cvt.rn.f16x2.f32 %0, %1, %2;" : "=r"(p) : "f"(hi), "f"(lo));
  return p;
}

// ---------------------------------------------------------------------------
// merged prep kernel: convx (all blocks) + weight/bias convert + rpb
// (first blocks double-duty). One launch instead of three.
// ---------------------------------------------------------------------------
__global__ void prep_all_kernel(const float* __restrict__ x,
                                const float* __restrict__ qkvw,
                                const float* __restrict__ projw,
                                const float* __restrict__ qb,
                                const float* __restrict__ vb,
                                const float* __restrict__ table) {
  int g = blockIdx.x * 256 + threadIdx.x;

  // ---- convx: x [B,H*W,C] fp32 -> g_xh [win*196, C] fp16 (gather fused) ----
  {
    int m = g / 96, kk = g - m * 96;               // g < M_*96 always (grid sized)
    int w = m / N_, n = m - w * N_;
    int b = w >> 4, wr = w & 15, wh = wr >> 2, ww = wr & 3;
    int ii = n / WS_, jj = n - ii * WS_;
    size_t xr = (size_t)b * (HH * WWp) + (size_t)(wh * WS_ + ii) * WWp + (ww * WS_ + jj);
    const float4* src = (const float4*)(x + xr * C + kk * 8);
    float4 v0 = src[0], v1 = src[1];
    union { int4 i4; __half2 h2v[4]; } o;
    o.h2v[0] = __floats2half2_rn(v0.x, v0.y);
    o.h2v[1] = __floats2half2_rn(v0.z, v0.w);
    o.h2v[2] = __floats2half2_rn(v1.x, v1.y);
    o.h2v[3] = __floats2half2_rn(v1.z, v1.w);
    *(int4*)(g_xh + (size_t)m * C + kk * 8) = o.i4;
  }

  // ---- weight/bias conversion ----
  if (g < 2304 * 768) g_wqkv[g] = __float2half(qkvw[g]);
  if (g < 768 * 768)  g_wproj[g] = __float2half(projw[g]);
  if (g < 2304) g_bqkv[g] = (g < 768) ? qb[g] : ((g < 1536) ? 0.0f : vb[g - 1536]);

  // ---- rpb, TILE-PERMUTED cols: j = 8*nb+2*tig+e stored at p = 8*tig+2*nb+e
  if (g < N_ * RLD) {
    int a = g / RLD, b = g - a * RLD;
    int j = b & 31;
    int p = 8 * ((j >> 1) & 3) + 2 * (j >> 3) + (j & 1);
    int bp = (b & ~31) + p;
    if (b < N_) {
      int i1 = a / WS_, j1 = a - i1 * WS_;
      int i2 = b / WS_, j2 = b - i2 * WS_;
      int idx = (i1 - i2 + WS_ - 1) * (2 * WS_ - 1) + (j1 - j2 + WS_ - 1);
#pragma unroll
      for (int hh = 0; hh < NH_; hh++)
        g_rpbh[(size_t)hh * N_ * RLD + a * RLD + bp] = __float2half(table[idx * NH_ + hh]);
    } else {
#pragma unroll
      for (int hh = 0; hh < NH_; hh++)
        g_rpbh[(size_t)hh * N_ * RLD + a * RLD + bp] = __float2half(0.0f);
    }
  }
}

// ---------------------------------------------------------------------------
// WMMA GEMM v8: gemm5 core + (a) cp.async prefetch deferred past the ks=0
// fragment loads (de-clumps LSU after the barrier), (b) single-phase epilogue
// (LDE=132, no mid-epilogue barriers). 2 CTAs/SM (2x67.6KB = 135KB smem).
// ---------------------------------------------------------------------------
template <int MODE>
__global__ __launch_bounds__(128, 2) void gemm8_kernel(const float* __restrict__ bias_in,
                                                       float* __restrict__ out_f) {
  constexpr int BM = 128, BN = 128, S = 3;
  constexpr int LDA = 40, LDB = 40, LDE = 132;
  constexpr int NKT = KQ / 32;
  constexpr int ABYTES = BM * LDA * 2;
  constexpr int STG = ABYTES + BN * LDB * 2;

  extern __shared__ __align__(16) char dsm[];
  float* ep = (float*)dsm;

  const __half* __restrict__ A  = (MODE == 0) ? g_xh : g_ao;
  const __half* __restrict__ Bw = (MODE == 0) ? g_wqkv : g_wproj;
  const int n0 = blockIdx.x * BN;
  const int m0 = blockIdx.y * BM;
  const int tid = threadIdx.x;
  const int warp = tid >> 5;
  const int wm = warp >> 1, wn = warp & 1;

  wmma::fragment<wmma::accumulator, 16, 16, 16, float> acc[4][4];
#pragma unroll
  for (int i = 0; i < 4; i++)
#pragma unroll
    for (int j = 0; j < 4; j++) wmma::fill_fragment(acc[i][j], 0.0f);

  auto load_stage = [&](int kt) {
    const int slot = kt % S;
    char* abase = dsm + slot * STG;
    char* bbase = abase + ABYTES;
    const char* ag = (const char*)(A + (size_t)m0 * KQ + kt * 32);
    const char* bg = (const char*)(Bw + (size_t)n0 * KQ + kt * 32);
#pragma unroll
    for (int i = 0; i < 4; i++) {
      int q = tid + i * 128; int r = q >> 2, co = q & 3;
      cpa16(smem_u32(abase + r * (LDA * 2) + co * 16),
            ag + (size_t)r * (KQ * 2) + co * 16, true);
    }
#pragma unroll
    for (int i = 0; i < 4; i++) {
      int q = tid + i * 128; int r = q >> 2, co = q & 3;
      cpa16(smem_u32(bbase + r * (LDB * 2) + co * 16),
            bg + (size_t)r * (KQ * 2) + co * 16, true);
    }
    asm volatile("cp.async.commit_group;" ::: "memory");
  };

  load_stage(0);
  load_stage(1);

  for (int kt = 0; kt < NKT; kt++) {
    if (kt < NKT - 1) asm volatile("cp.async.wait_group 1;" ::: "memory");
    else              asm volatile("cp.async.wait_group 0;" ::: "memory");
    __syncthreads();

    const int slot = kt % S;
    const __half* sA = (const __half*)(dsm + slot * STG);
    const __half* sB = (const __half*)(dsm + slot * STG + ABYTES);

    // ---- ks = 0: fragment loads first, THEN issue next-stage cp.async ----
    {
      wmma::fragment<wmma::matrix_a, 16, 16, 16, __half, wmma::row_major> af[4];
      wmma::fragment<wmma::matrix_b, 16, 16, 16, __half, wmma::col_major> bf[4];
#pragma unroll
      for (int i = 0; i < 4; i++)
        wmma::load_matrix_sync(af[i], &sA[(wm * 64 + i * 16) * LDA], LDA);
#pragma unroll
      for (int j = 0; j < 4; j++)
        wmma::load_matrix_sync(bf[j], &sB[(wn * 64 + j * 16) * LDB], LDB);

      if (kt + 2 < NKT) load_stage(kt + 2);   // LSU now free of the LDSM burst

#pragma unroll
      for (int i = 0; i < 4; i++)
#pragma unroll
        for (int j = 0; j < 4; j++)
          wmma::mma_sync(acc[i][j], af[i], bf[j], acc[i][j]);
    }
    // ---- ks = 1 ----
    {
      wmma::fragment<wmma::matrix_a, 16, 16, 16, __half, wmma::row_major> af[4];
      wmma::fragment<wmma::matrix_b, 16, 16, 16, __half, wmma::col_major> bf[4];
#pragma unroll
      for (int i = 0; i < 4; i++)
        wmma::load_matrix_sync(af[i], &sA[(wm * 64 + i * 16) * LDA + 16], LDA);
#pragma unroll
      for (int j = 0; j < 4; j++)
        wmma::load_matrix_sync(bf[j], &sB[(wn * 64 + j * 16) * LDB + 16], LDB);
#pragma unroll
      for (int i = 0; i < 4; i++)
#pragma unroll
        for (int j = 0; j < 4; j++)
          wmma::mma_sync(acc[i][j], af[i], bf[j], acc[i][j]);
    }
  }

  // ---- single-phase epilogue: all frags -> smem -> fused bias + scatter ----
  __syncthreads();
#pragma unroll
  for (int i = 0; i < 4; i++)
#pragma unroll
    for (int j = 0; j < 4; j++)
      wmma::store_matrix_sync(&ep[(wm * 64 + i * 16) * LDE + wn * 64 + j * 16],
                              acc[i][j], LDE, wmma::mem_row_major);
  __syncthreads();
#pragma unroll 4
  for (int it = 0; it < 64; it++) {                  // 128x128 / 2 = 8192 pairs
    int idx = it * 128 + tid;
    int r = idx >> 6, ccp = idx & 63;
    int cc = ccp * 2;
    int m = m0 + r;
    int c = n0 + cc;
    float v0 = ep[r * LDE + cc];
    float v1 = ep[r * LDE + cc + 1];
    int w = m / N_, n = m - w * N_;
    if (MODE == 0) {
      v0 += g_bqkv[c];
      v1 += g_bqkv[c + 1];
      int sec = c / 768, cu = c - sec * 768;
      int h = cu >> 6, d = cu & 63;
      __half* dst = ((sec == 0) ? g_q : (sec == 1) ? g_k : g_v) +
                    ((size_t)(w * NH_ + h) * N_ + n) * HD + d;
      float sc = (sec == 0) ? 0.125f : 1.0f;
      *(__half2*)dst = __floats2half2_rn(v0 * sc, v1 * sc);
    } else {
      v0 += bias_in[c];
      v1 += bias_in[c + 1];
      int b = w >> 4, wr = w & 15, wh = wr >> 2, ww = wr & 3;
      int ii = n / WS_, jj = n - ii * WS_;
      size_t xr = (size_t)b * (HH * WWp) + (size_t)(wh * WS_ + ii) * WWp + (ww * WS_ + jj);
      *(float2*)(out_f + xr * C + c) = make_float2(v0, v1);
    }
  }
}

// ---------------------------------------------------------------------------
// attention v7 (R12 winner, verbatim): 128-thread CTAs, 2 q-blocks per (w,h),
// register-resident flash chain, vectorized tile-permuted rpb prefetch.
// ---------------------------------------------------------------------------
__global__ __launch_bounds__(128) void attn_kernel() {
  constexpr int KT = 32, NT = 7;
  constexpr int LQB = 144;
  constexpr int KBYTES = KT * LQB;              // 4608
  constexpr int STGB = 2 * KBYTES;              // 9216 (K + V)
  constexpr int QOFF = 3 * STGB;                // 27648

  extern __shared__ __align__(16) char asm_[];
  const uint32_t smb = smem_u32(asm_);

  const int h = blockIdx.x, w = blockIdx.y, qc = blockIdx.z;
  const int tid = threadIdx.x, warp = tid >> 5, lane = tid & 31;
  const int tig = lane & 3, tq = lane >> 2;
  const int row0 = qc * 128;

  const size_t base = ((size_t)w * NH_ + h) * N_ * HD;
  const __half* Qg = g_q + base;
  const __half* Kg = g_k + base;
  const __half* Vg = g_v + base;
  const __half* Rg = g_rpbh + (size_t)h * N_ * RLD;

#pragma unroll
  for (int i = 0; i < 8; i++) {
    int idx = tid + i * 128;
    int r = idx >> 3, c = idx & 7;
    int n = row0 + r;
    cpa16(smb + QOFF + r * LQB + c * 16, Qg + (size_t)n * HD + c * 8, n < N_);
  }
  asm volatile("cp.async.commit_group;" ::: "memory");

  auto load_stage = [&](int t) {
    const uint32_t sb = smb + (t % 3) * STGB;
#pragma unroll
    for (int i = 0; i < 2; i++) {
      int idx = tid + i * 128;
      int r = idx >> 3, c = idx & 7;
      int jg = t * KT + r;
      cpa16(sb + r * LQB + c * 16, Kg + (size_t)jg * HD + c * 8, jg < N_);
      cpa16(sb + KBYTES + r * LQB + c * 16, Vg + (size_t)jg * HD + c * 8, jg < N_);
    }
    asm volatile("cp.async.commit_group;" ::: "memory");
  };

  load_stage(0);
  load_stage(1);

  asm volatile("cp.async.wait_group 2;" ::: "memory");
  __syncthreads();
  uint32_t qa[2][4][4];
#pragma unroll
  for (int g = 0; g < 2; g++)
#pragma unroll
    for (int kk = 0; kk < 4; kk++) {
      uint32_t addr = smb + QOFF + (warp * 32 + g * 16 + (lane & 15)) * LQB +
                      (kk * 16 + ((lane >> 4) << 3)) * 2;
      ldx4(qa[g][kk], addr);
    }

  float oacc[2][8][4];
#pragma unroll
  for (int g = 0; g < 2; g++)
#pragma unroll
    for (int d = 0; d < 8; d++)
#pragma unroll
      for (int i = 0; i < 4; i++) oacc[g][d][i] = 0.0f;
  float rsum[2][2] = {{0.0f, 0.0f}, {0.0f, 0.0f}};

  for (int t = 0; t < NT; t++) {
    if (t < NT - 1) asm volatile("cp.async.wait_group 1;" ::: "memory");
    else            asm volatile("cp.async.wait_group 0;" ::: "memory");
    __syncthreads();
    if (t + 2 < NT) load_stage(t + 2);

    const uint32_t sb = smb + (t % 3) * STGB;

    uint32_t rpre[2][2][4];
#pragma unroll
    for (int g = 0; g < 2; g++)
#pragma unroll
      for (int p2 = 0; p2 < 2; p2++) {
        int rr = row0 + warp * 32 + g * 16 + tq + p2 * 8;
        int4 rq = make_int4(0, 0, 0, 0);
        if (rr < N_)
          rq = *(const int4*)(Rg + (size_t)rr * RLD + t * KT + 8 * tig);
        rpre[g][p2][0] = (uint32_t)rq.x;
        rpre[g][p2][1] = (uint32_t)rq.y;
        rpre[g][p2][2] = (uint32_t)rq.z;
        rpre[g][p2][3] = (uint32_t)rq.w;
      }

    uint32_t pa[2][2][4];
#pragma unroll
    for (int nb = 0; nb < 4; nb++) {
      float s0[4] = {0, 0, 0, 0}, s1[4] = {0, 0, 0, 0};
#pragma unroll
      for (int kk = 0; kk < 4; kk++) {
        uint32_t kf2[2];
        uint32_t ka = sb + (nb * 8 + (lane & 7)) * LQB +
                      (kk * 16 + (((lane >> 3) & 1) << 3)) * 2;
        ldx2(kf2, ka);
        mma16816(s0, qa[0][kk], kf2);
        mma16816(s1, qa[1][kk], kf2);
      }
      const int j0 = t * KT + nb * 8 + 2 * tig;
      const bool jv = (j0 < N_);
#pragma unroll
      for (int g = 0; g < 2; g++) {
        const float* sg = (g == 0) ? s0 : s1;
        float e0 = 0, e1 = 0, e2 = 0, e3 = 0;
        if (jv) {
          float2 fl = __half22float2(*(const __half2*)&rpre[g][0][nb]);
          float2 fh = __half22float2(*(const __half2*)&rpre[g][1][nb]);
          e0 = __expf(sg[0] + fl.x);
          e1 = __expf(sg[1] + fl.y);
          e2 = __expf(sg[2] + fh.x);
          e3 = __expf(sg[3] + fh.y);
        }
        rsum[g][0] += e0 + e1;
        rsum[g][1] += e2 + e3;
        pa[g][nb >> 1][(nb & 1) * 2 + 0] = packh2(e0, e1);
        pa[g][nb >> 1][(nb & 1) * 2 + 1] = packh2(e2, e3);
      }
    }

#pragma unroll
    for (int kb = 0; kb < 2; kb++)
#pragma unroll
      for (int dh = 0; dh < 4; dh++) {
        uint32_t vt[4];
        uint32_t va = sb + KBYTES + (kb * 16 + (lane & 15)) * LQB +
                      (dh * 16 + ((lane >> 4) << 3)) * 2;
        ldx4t(vt, va);
        mma16816(oacc[0][2 * dh],     pa[0][kb], vt + 0);
        mma16816(oacc[0][2 * dh + 1], pa[0][kb], vt + 2);
        mma16816(oacc[1][2 * dh],     pa[1][kb], vt + 0);
        mma16816(oacc[1][2 * dh + 1], pa[1][kb], vt + 2);
      }
  }

#pragma unroll
  for (int g = 0; g < 2; g++) {
    float slo = rsum[g][0];
    slo += __shfl_xor_sync(0xFFFFFFFFu, slo, 1);
    slo += __shfl_xor_sync(0xFFFFFFFFu, slo, 2);
    float shi = rsum[g][1];
    shi += __shfl_xor_sync(0xFFFFFFFFu, shi, 1);
    shi += __shfl_xor_sync(0xFFFFFFFFu, shi, 2);
    float ilo = 1.0f / slo, ihi = 1.0f / shi;
    int nlo = row0 + warp * 32 + g * 16 + tq;
    int nhi = nlo + 8;
    __half* rowlo = g_ao + ((size_t)w * N_ + nlo) * C + h * HD;
    __half* rowhi = g_ao + ((size_t)w * N_ + nhi) * C + h * HD;
#pragma unroll
    for (int db = 0; db < 8; db++) {
      int col = db * 8 + 2 * tig;
      if (nlo < N_)
        *(__half2*)(rowlo + col) =
            __floats2half2_rn(oacc[g][db][0] * ilo, oacc[g][db][1] * ilo);
      if (nhi < N_)
        *(__half2*)(rowhi + col) =
            __floats2half2_rn(oacc[g][db][2] * ihi, oacc[g][db][3] * ihi);
    }
  }
}

// ---------------------------------------------------------------------------
extern "C" void kernel_launch(void* const* d_in, const int* in_sizes, int n_in,
                              void* d_out, int out_size) {
  const float* x     = (const float*)d_in[0];
  const float* qkvw  = (const float*)d_in[1];
  const float* qb    = (const float*)d_in[2];
  const float* vb    = (const float*)d_in[3];
  const float* table = (const float*)d_in[4];
  const float* projw = (const float*)d_in[5];
  const float* projb = (const float*)d_in[6];
  float* out = (float*)d_out;
  (void)in_sizes; (void)n_in; (void)out_size;

  const int DSMEM_G = 128 * 132 * 4;                 // 67584 (>= 3 stages 61440)
  const int DSMEM_A = 3 * 9216 + 128 * 144;          // 46080
  cudaFuncSetAttribute(gemm8_kernel<0>, cudaFuncAttributeMaxDynamicSharedMemorySize, DSMEM_G);
  cudaFuncSetAttribute(gemm8_kernel<1>, cudaFuncAttributeMaxDynamicSharedMemorySize, DSMEM_G);
  cudaFuncSetAttribute(attn_kernel, cudaFuncAttributeMaxDynamicSharedMemorySize, DSMEM_A);

  prep_all_kernel<<<(M_ * 96) / 256, 256>>>(x, qkvw, projw, qb, vb, table);
  gemm8_kernel<0><<<dim3(2304 / 128, M_ / 128), 128, DSMEM_G>>>(nullptr, nullptr);
  attn_kernel<<<dim3(NH_, NWIN, 2), 128, DSMEM_A>>>();
  gemm8_kernel<1><<<dim3(768 / 128, M_ / 128), 128, DSMEM_G>>>(projb, out);
}

// round 14
// speedup vs baseline: 1.0338x; 1.0338x over previous
#include <cuda_runtime.h>
#include <cuda_fp16.h>
#include <mma.h>
#include <cstdint>

using namespace nvcuda;

// Problem constants (static shapes)
constexpr int HH   = 56;
constexpr int WWp  = 56;
constexpr int C    = 768;
constexpr int NH_  = 12;
constexpr int HD   = 64;
constexpr int WS_  = 14;
constexpr int N_   = 196;        // tokens per window
constexpr int NWIN = 256;        // 16 batch * 16 windows
constexpr int M_   = NWIN * N_;  // 50176 rows
constexpr int KQ   = 768;
constexpr int RLD  = 224;        // padded rpb row stride (halfs) = 7 tiles x 32

// -------- device scratch (allocation-free rule: __device__ globals) --------
__device__ __half g_xh[(size_t)M_ * C];          // window-ordered fp16 x
__device__ __half g_wqkv[2304 * 768];
__device__ __half g_wproj[768 * 768];
__device__ float  g_bqkv[2304];
__device__ __half g_q[(size_t)NWIN * NH_ * N_ * HD];
__device__ __half g_k[(size_t)NWIN * NH_ * N_ * HD];
__device__ __half g_v[(size_t)NWIN * NH_ * N_ * HD];
__device__ __half g_rpbh[(size_t)NH_ * N_ * RLD];  // half, tile-permuted cols (L2-resident)
__device__ __half g_ao[(size_t)M_ * C];          // attention output (proj input)

// ---------------- raw-PTX helpers (all sm_80-level; safe on compute_103) ----
__device__ __forceinline__ uint32_t smem_u32(const void* p) {
  uint32_t a;
  asm("{ .reg .u64 t; cvta.to.shared.u64 t, %1; cvt.u32.u64 %0, t; }" : "=r"(a) : "l"(p));
  return a;
}
__device__ __forceinline__ void cpa16(uint32_t dst, const void* src, bool valid) {
  int sz = valid ? 16 : 0;
  asm volatile("cp.async.cg.shared.global [%0], [%1], 16, %2;"
               :: "r"(dst), "l"(src), "r"(sz) : "memory");
}
__device__ __forceinline__ void ldx4(uint32_t* r, uint32_t a) {
  asm volatile("ldmatrix.sync.aligned.m8n8.x4.shared.b16 {%0,%1,%2,%3}, [%4];"
               : "=r"(r[0]), "=r"(r[1]), "=r"(r[2]), "=r"(r[3]) : "r"(a));
}
__device__ __forceinline__ void ldx4t(uint32_t* r, uint32_t a) {
  asm volatile("ldmatrix.sync.aligned.m8n8.x4.trans.shared.b16 {%0,%1,%2,%3}, [%4];"
               : "=r"(r[0]), "=r"(r[1]), "=r"(r[2]), "=r"(r[3]) : "r"(a));
}
__device__ __forceinline__ void ldx2(uint32_t* r, uint32_t a) {
  asm volatile("ldmatrix.sync.aligned.m8n8.x2.shared.b16 {%0,%1}, [%2];"
               : "=r"(r[0]), "=r"(r[1]) : "r"(a));
}
__device__ __forceinline__ void mma16816(float* d, const uint32_t* a, const uint32_t* b) {
  asm volatile("mma.sync.aligned.m16n8k16.row.col.f32.f16.f16.f32 "
               "{%0,%1,%2,%3}, {%4,%5,%6,%7}, {%8,%9}, {%0,%1,%2,%3};"
               : "+f"(d[0]), "+f"(d[1]), "+f"(d[2]), "+f"(d[3])
               : "r"(a[0]), "r"(a[1]), "r"(a[2]), "r"(a[3]), "r"(b[0]), "r"(b[1]));
}
__device__ __forceinline__ uint32_t packh2(float lo, float hi) {
  uint32_t p;
  asm("cvt.rn.f16x2.f32 %0, %1, %2;" : "=r"(p) : "f"(hi), "f"(lo));
  return p;
}

// ---------------------------------------------------------------------------
// merged prep kernel: convx (all blocks) + weight/bias convert + rpb
// (first blocks double-duty). One launch instead of three.
// ---------------------------------------------------------------------------
__global__ void prep_all_kernel(const float* __restrict__ x,
                                const float* __restrict__ qkvw,
                                const float* __restrict__ projw,
                                const float* __restrict__ qb,
                                const float* __restrict__ vb,
                                const float* __restrict__ table) {
  int g = blockIdx.x * 256 + threadIdx.x;

  // ---- convx: x [B,H*W,C] fp32 -> g_xh [win*196, C] fp16 (gather fused) ----
  {
    int m = g / 96, kk = g - m * 96;               // g < M_*96 always (grid sized)
    int w = m / N_, n = m - w * N_;
    int b = w >> 4, wr = w & 15, wh = wr >> 2, ww = wr & 3;
    int ii = n / WS_, jj = n - ii * WS_;
    size_t xr = (size_t)b * (HH * WWp) + (size_t)(wh * WS_ + ii) * WWp + (ww * WS_ + jj);
    const float4* src = (const float4*)(x + xr * C + kk * 8);
    float4 v0 = src[0], v1 = src[1];
    union { int4 i4; __half2 h2v[4]; } o;
    o.h2v[0] = __floats2half2_rn(v0.x, v0.y);
    o.h2v[1] = __floats2half2_rn(v0.z, v0.w);
    o.h2v[2] = __floats2half2_rn(v1.x, v1.y);
    o.h2v[3] = __floats2half2_rn(v1.z, v1.w);
    *(int4*)(g_xh + (size_t)m * C + kk * 8) = o.i4;
  }

  // ---- weight/bias conversion ----
  if (g < 2304 * 768) g_wqkv[g] = __float2half(qkvw[g]);
  if (g < 768 * 768)  g_wproj[g] = __float2half(projw[g]);
  if (g < 2304) g_bqkv[g] = (g < 768) ? qb[g] : ((g < 1536) ? 0.0f : vb[g - 1536]);

  // ---- rpb, TILE-PERMUTED cols: j = 8*nb+2*tig+e stored at p = 8*tig+2*nb+e
  if (g < N_ * RLD) {
    int a = g / RLD, b = g - a * RLD;
    int j = b & 31;
    int p = 8 * ((j >> 1) & 3) + 2 * (j >> 3) + (j & 1);
    int bp = (b & ~31) + p;
    if (b < N_) {
      int i1 = a / WS_, j1 = a - i1 * WS_;
      int i2 = b / WS_, j2 = b - i2 * WS_;
      int idx = (i1 - i2 + WS_ - 1) * (2 * WS_ - 1) + (j1 - j2 + WS_ - 1);
#pragma unroll
      for (int hh = 0; hh < NH_; hh++)
        g_rpbh[(size_t)hh * N_ * RLD + a * RLD + bp] = __float2half(table[idx * NH_ + hh]);
    } else {
#pragma unroll
      for (int hh = 0; hh < NH_; hh++)
        g_rpbh[(size_t)hh * N_ * RLD + a * RLD + bp] = __float2half(0.0f);
    }
  }
}

// ---------------------------------------------------------------------------
// WMMA GEMM (R6/R9/R12 winner, verbatim): CTA 128 thr, tile 128x128, warp
// tile 64x64, BK=32, 3-stage cp.async, single barrier per k-iter, 2 CTAs/SM.
// ---------------------------------------------------------------------------
template <int MODE>
__global__ __launch_bounds__(128, 2) void gemm5_kernel(const float* __restrict__ bias_in,
                                                       float* __restrict__ out_f) {
  constexpr int BM = 128, BN = 128, S = 3;
  constexpr int LDA = 40, LDB = 40, LDE = 68;
  constexpr int NKT = KQ / 32;
  constexpr int ABYTES = BM * LDA * 2;
  constexpr int STG = ABYTES + BN * LDB * 2;

  extern __shared__ __align__(16) char dsm[];
  float* ep = (float*)dsm;

  const __half* __restrict__ A  = (MODE == 0) ? g_xh : g_ao;
  const __half* __restrict__ Bw = (MODE == 0) ? g_wqkv : g_wproj;
  const int n0 = blockIdx.x * BN;
  const int m0 = blockIdx.y * BM;
  const int tid = threadIdx.x;
  const int warp = tid >> 5;
  const int wm = warp >> 1, wn = warp & 1;

  wmma::fragment<wmma::accumulator, 16, 16, 16, float> acc[4][4];
#pragma unroll
  for (int i = 0; i < 4; i++)
#pragma unroll
    for (int j = 0; j < 4; j++) wmma::fill_fragment(acc[i][j], 0.0f);

  auto load_stage = [&](int kt) {
    const int slot = kt % S;
    char* abase = dsm + slot * STG;
    char* bbase = abase + ABYTES;
    const char* ag = (const char*)(A + (size_t)m0 * KQ + kt * 32);
    const char* bg = (const char*)(Bw + (size_t)n0 * KQ + kt * 32);
#pragma unroll
    for (int i = 0; i < 4; i++) {
      int q = tid + i * 128; int r = q >> 2, co = q & 3;
      cpa16(smem_u32(abase + r * (LDA * 2) + co * 16),
            ag + (size_t)r * (KQ * 2) + co * 16, true);
    }
#pragma unroll
    for (int i = 0; i < 4; i++) {
      int q = tid + i * 128; int r = q >> 2, co = q & 3;
      cpa16(smem_u32(bbase + r * (LDB * 2) + co * 16),
            bg + (size_t)r * (KQ * 2) + co * 16, true);
    }
    asm volatile("cp.async.commit_group;" ::: "memory");
  };

  load_stage(0);
  load_stage(1);

  for (int kt = 0; kt < NKT; kt++) {
    if (kt < NKT - 1) asm volatile("cp.async.wait_group 1;" ::: "memory");
    else              asm volatile("cp.async.wait_group 0;" ::: "memory");
    __syncthreads();
    if (kt + 2 < NKT) load_stage(kt + 2);

    const int slot = kt % S;
    const __half* sA = (const __half*)(dsm + slot * STG);
    const __half* sB = (const __half*)(dsm + slot * STG + ABYTES);
#pragma unroll
    for (int ks = 0; ks < 2; ks++) {
      wmma::fragment<wmma::matrix_a, 16, 16, 16, __half, wmma::row_major> af[4];
      wmma::fragment<wmma::matrix_b, 16, 16, 16, __half, wmma::col_major> bf[4];
#pragma unroll
      for (int i = 0; i < 4; i++)
        wmma::load_matrix_sync(af[i], &sA[(wm * 64 + i * 16) * LDA + ks * 16], LDA);
#pragma unroll
      for (int j = 0; j < 4; j++)
        wmma::load_matrix_sync(bf[j], &sB[(wn * 64 + j * 16) * LDB + ks * 16], LDB);
#pragma unroll
      for (int i = 0; i < 4; i++)
#pragma unroll
        for (int j = 0; j < 4; j++)
          wmma::mma_sync(acc[i][j], af[i], bf[j], acc[i][j]);
    }
  }

#pragma unroll 1
  for (int p = 0; p < 2; p++) {
    __syncthreads();
    if (wn == p) {
#pragma unroll
      for (int i = 0; i < 4; i++)
#pragma unroll
        for (int j = 0; j < 4; j++)
          wmma::store_matrix_sync(&ep[(wm * 64 + i * 16) * LDE + j * 16],
                                  acc[i][j], LDE, wmma::mem_row_major);
    }
    __syncthreads();
#pragma unroll 4
    for (int it = 0; it < 32; it++) {
      int idx = it * 128 + tid;
      int r = idx >> 5, ccp = idx & 31;
      int cc = ccp * 2;
      int m = m0 + r;
      int c = n0 + p * 64 + cc;
      float v0 = ep[r * LDE + cc];
      float v1 = ep[r * LDE + cc + 1];
      int w = m / N_, n = m - w * N_;
      if (MODE == 0) {
        v0 += g_bqkv[c];
        v1 += g_bqkv[c + 1];
        int sec = c / 768, cu = c - sec * 768;
        int h = cu >> 6, d = cu & 63;
        __half* dst = ((sec == 0) ? g_q : (sec == 1) ? g_k : g_v) +
                      ((size_t)(w * NH_ + h) * N_ + n) * HD + d;
        float sc = (sec == 0) ? 0.125f : 1.0f;
        *(__half2*)dst = __floats2half2_rn(v0 * sc, v1 * sc);
      } else {
        v0 += bias_in[c];
        v1 += bias_in[c + 1];
        int b = w >> 4, wr = w & 15, wh = wr >> 2, ww = wr & 3;
        int ii = n / WS_, jj = n - ii * WS_;
        size_t xr = (size_t)b * (HH * WWp) + (size_t)(wh * WS_ + ii) * WWp + (ww * WS_ + jj);
        *(float2*)(out_f + xr * C + c) = make_float2(v0, v1);
      }
    }
  }
}

// ---------------------------------------------------------------------------
// attention v7 (R12 winner, verbatim): 128-thread CTAs, 2 q-blocks per (w,h),
// register-resident flash chain, vectorized tile-permuted rpb prefetch.
// ---------------------------------------------------------------------------
__global__ __launch_bounds__(128) void attn_kernel() {
  constexpr int KT = 32, NT = 7;
  constexpr int LQB = 144;
  constexpr int KBYTES = KT * LQB;              // 4608
  constexpr int STGB = 2 * KBYTES;              // 9216 (K + V)
  constexpr int QOFF = 3 * STGB;                // 27648

  extern __shared__ __align__(16) char asm_[];
  const uint32_t smb = smem_u32(asm_);

  const int h = blockIdx.x, w = blockIdx.y, qc = blockIdx.z;
  const int tid = threadIdx.x, warp = tid >> 5, lane = tid & 31;
  const int tig = lane & 3, tq = lane >> 2;
  const int row0 = qc * 128;

  const size_t base = ((size_t)w * NH_ + h) * N_ * HD;
  const __half* Qg = g_q + base;
  const __half* Kg = g_k + base;
  const __half* Vg = g_v + base;
  const __half* Rg = g_rpbh + (size_t)h * N_ * RLD;

#pragma unroll
  for (int i = 0; i < 8; i++) {
    int idx = tid + i * 128;
    int r = idx >> 3, c = idx & 7;
    int n = row0 + r;
    cpa16(smb + QOFF + r * LQB + c * 16, Qg + (size_t)n * HD + c * 8, n < N_);
  }
  asm volatile("cp.async.commit_group;" ::: "memory");

  auto load_stage = [&](int t) {
    const uint32_t sb = smb + (t % 3) * STGB;
#pragma unroll
    for (int i = 0; i < 2; i++) {
      int idx = tid + i * 128;
      int r = idx >> 3, c = idx & 7;
      int jg = t * KT + r;
      cpa16(sb + r * LQB + c * 16, Kg + (size_t)jg * HD + c * 8, jg < N_);
      cpa16(sb + KBYTES + r * LQB + c * 16, Vg + (size_t)jg * HD + c * 8, jg < N_);
    }
    asm volatile("cp.async.commit_group;" ::: "memory");
  };

  load_stage(0);
  load_stage(1);

  asm volatile("cp.async.wait_group 2;" ::: "memory");
  __syncthreads();
  uint32_t qa[2][4][4];
#pragma unroll
  for (int g = 0; g < 2; g++)
#pragma unroll
    for (int kk = 0; kk < 4; kk++) {
      uint32_t addr = smb + QOFF + (warp * 32 + g * 16 + (lane & 15)) * LQB +
                      (kk * 16 + ((lane >> 4) << 3)) * 2;
      ldx4(qa[g][kk], addr);
    }

  float oacc[2][8][4];
#pragma unroll
  for (int g = 0; g < 2; g++)
#pragma unroll
    for (int d = 0; d < 8; d++)
#pragma unroll
      for (int i = 0; i < 4; i++) oacc[g][d][i] = 0.0f;
  float rsum[2][2] = {{0.0f, 0.0f}, {0.0f, 0.0f}};

  for (int t = 0; t < NT; t++) {
    if (t < NT - 1) asm volatile("cp.async.wait_group 1;" ::: "memory");
    else            asm volatile("cp.async.wait_group 0;" ::: "memory");
    __syncthreads();
    if (t + 2 < NT) load_stage(t + 2);

    const uint32_t sb = smb + (t % 3) * STGB;

    uint32_t rpre[2][2][4];
#pragma unroll
    for (int g = 0; g < 2; g++)
#pragma unroll
      for (int p2 = 0; p2 < 2; p2++) {
        int rr = row0 + warp * 32 + g * 16 + tq + p2 * 8;
        int4 rq = make_int4(0, 0, 0, 0);
        if (rr < N_)
          rq = *(const int4*)(Rg + (size_t)rr * RLD + t * KT + 8 * tig);
        rpre[g][p2][0] = (uint32_t)rq.x;
        rpre[g][p2][1] = (uint32_t)rq.y;
        rpre[g][p2][2] = (uint32_t)rq.z;
        rpre[g][p2][3] = (uint32_t)rq.w;
      }

    uint32_t pa[2][2][4];
#pragma unroll
    for (int nb = 0; nb < 4; nb++) {
      float s0[4] = {0, 0, 0, 0}, s1[4] = {0, 0, 0, 0};
#pragma unroll
      for (int kk = 0; kk < 4; kk++) {
        uint32_t kf2[2];
        uint32_t ka = sb + (nb * 8 + (lane & 7)) * LQB +
                      (kk * 16 + (((lane >> 3) & 1) << 3)) * 2;
        ldx2(kf2, ka);
        mma16816(s0, qa[0][kk], kf2);
        mma16816(s1, qa[1][kk], kf2);
      }
      const int j0 = t * KT + nb * 8 + 2 * tig;
      const bool jv = (j0 < N_);
#pragma unroll
      for (int g = 0; g < 2; g++) {
        const float* sg = (g == 0) ? s0 : s1;
        float e0 = 0, e1 = 0, e2 = 0, e3 = 0;
        if (jv) {
          float2 fl = __half22float2(*(const __half2*)&rpre[g][0][nb]);
          float2 fh = __half22float2(*(const __half2*)&rpre[g][1][nb]);
          e0 = __expf(sg[0] + fl.x);
          e1 = __expf(sg[1] + fl.y);
          e2 = __expf(sg[2] + fh.x);
          e3 = __expf(sg[3] + fh.y);
        }
        rsum[g][0] += e0 + e1;
        rsum[g][1] += e2 + e3;
        pa[g][nb >> 1][(nb & 1) * 2 + 0] = packh2(e0, e1);
        pa[g][nb >> 1][(nb & 1) * 2 + 1] = packh2(e2, e3);
      }
    }

#pragma unroll
    for (int kb = 0; kb < 2; kb++)
#pragma unroll
      for (int dh = 0; dh < 4; dh++) {
        uint32_t vt[4];
        uint32_t va = sb + KBYTES + (kb * 16 + (lane & 15)) * LQB +
                      (dh * 16 + ((lane >> 4) << 3)) * 2;
        ldx4t(vt, va);
        mma16816(oacc[0][2 * dh],     pa[0][kb], vt + 0);
        mma16816(oacc[0][2 * dh + 1], pa[0][kb], vt + 2);
        mma16816(oacc[1][2 * dh],     pa[1][kb], vt + 0);
        mma16816(oacc[1][2 * dh + 1], pa[1][kb], vt + 2);
      }
  }

#pragma unroll
  for (int g = 0; g < 2; g++) {
    float slo = rsum[g][0];
    slo += __shfl_xor_sync(0xFFFFFFFFu, slo, 1);
    slo += __shfl_xor_sync(0xFFFFFFFFu, slo, 2);
    float shi = rsum[g][1];
    shi += __shfl_xor_sync(0xFFFFFFFFu, shi, 1);
    shi += __shfl_xor_sync(0xFFFFFFFFu, shi, 2);
    float ilo = 1.0f / slo, ihi = 1.0f / shi;
    int nlo = row0 + warp * 32 + g * 16 + tq;
    int nhi = nlo + 8;
    __half* rowlo = g_ao + ((size_t)w * N_ + nlo) * C + h * HD;
    __half* rowhi = g_ao + ((size_t)w * N_ + nhi) * C + h * HD;
#pragma unroll
    for (int db = 0; db < 8; db++) {
      int col = db * 8 + 2 * tig;
      if (nlo < N_)
        *(__half2*)(rowlo + col) =
            __floats2half2_rn(oacc[g][db][0] * ilo, oacc[g][db][1] * ilo);
      if (nhi < N_)
        *(__half2*)(rowhi + col) =
            __floats2half2_rn(oacc[g][db][2] * ihi, oacc[g][db][3] * ihi);
    }
  }
}

// ---------------------------------------------------------------------------
extern "C" void kernel_launch(void* const* d_in, const int* in_sizes, int n_in,
                              void* d_out, int out_size) {
  const float* x     = (const float*)d_in[0];
  const float* qkvw  = (const float*)d_in[1];
  const float* qb    = (const float*)d_in[2];
  const float* vb    = (const float*)d_in[3];
  const float* table = (const float*)d_in[4];
  const float* projw = (const float*)d_in[5];
  const float* projb = (const float*)d_in[6];
  float* out = (float*)d_out;
  (void)in_sizes; (void)n_in; (void)out_size;

  const int DSMEM_G = 3 * 20480;                     // 61440
  const int DSMEM_A = 3 * 9216 + 128 * 144;          // 46080
  cudaFuncSetAttribute(gemm5_kernel<0>, cudaFuncAttributeMaxDynamicSharedMemorySize, DSMEM_G);
  cudaFuncSetAttribute(gemm5_kernel<1>, cudaFuncAttributeMaxDynamicSharedMemorySize, DSMEM_G);
  cudaFuncSetAttribute(attn_kernel, cudaFuncAttributeMaxDynamicSharedMemorySize, DSMEM_A);

  prep_all_kernel<<<(M_ * 96) / 256, 256>>>(x, qkvw, projw, qb, vb, table);
  gemm5_kernel<0><<<dim3(2304 / 128, M_ / 128), 128, DSMEM_G>>>(nullptr, nullptr);
  attn_kernel<<<dim3(NH_, NWIN, 2), 128, DSMEM_A>>>();
  gemm5_kernel<1><<<dim3(768 / 128, M_ / 128), 128, DSMEM_G>>>(projb, out);
}

// round 15
// speedup vs baseline: 1.0383x; 1.0044x over previous
#include <cuda_runtime.h>
#include <cuda_fp16.h>
#include <mma.h>
#include <cstdint>

using namespace nvcuda;

// Problem constants (static shapes)
constexpr int HH   = 56;
constexpr int WWp  = 56;
constexpr int C    = 768;
constexpr int NH_  = 12;
constexpr int HD   = 64;
constexpr int WS_  = 14;
constexpr int N_   = 196;        // tokens per window
constexpr int NWIN = 256;        // 16 batch * 16 windows
constexpr int M_   = NWIN * N_;  // 50176 rows
constexpr int KQ   = 768;
constexpr int RLD  = 224;        // padded rpb row stride (halfs) = 7 tiles x 32
constexpr float L2E = 1.4426950408889634f;

// -------- device scratch (allocation-free rule: __device__ globals) --------
__device__ __half g_xh[(size_t)M_ * C];          // window-ordered fp16 x
__device__ __half g_wqkv[2304 * 768];
__device__ __half g_wproj[768 * 768];
__device__ float  g_bqkv[2304];
__device__ __half g_q[(size_t)NWIN * NH_ * N_ * HD];   // pre-scaled by 0.125*log2e
__device__ __half g_k[(size_t)NWIN * NH_ * N_ * HD];
__device__ __half g_v[(size_t)NWIN * NH_ * N_ * HD];
__device__ __half g_rpbh[(size_t)NH_ * N_ * RLD];  // half * log2e, tile-permuted cols
__device__ __half g_ao[(size_t)M_ * C];          // attention output (proj input)

// ---------------- raw-PTX helpers (all sm_80-level; safe on compute_103) ----
__device__ __forceinline__ uint32_t smem_u32(const void* p) {
  uint32_t a;
  asm("{ .reg .u64 t; cvta.to.shared.u64 t, %1; cvt.u32.u64 %0, t; }" : "=r"(a) : "l"(p));
  return a;
}
__device__ __forceinline__ void cpa16(uint32_t dst, const void* src, bool valid) {
  int sz = valid ? 16 : 0;
  asm volatile("cp.async.cg.shared.global [%0], [%1], 16, %2;"
               :: "r"(dst), "l"(src), "r"(sz) : "memory");
}
__device__ __forceinline__ void ldx4(uint32_t* r, uint32_t a) {
  asm volatile("ldmatrix.sync.aligned.m8n8.x4.shared.b16 {%0,%1,%2,%3}, [%4];"
               : "=r"(r[0]), "=r"(r[1]), "=r"(r[2]), "=r"(r[3]) : "r"(a));
}
__device__ __forceinline__ void ldx4t(uint32_t* r, uint32_t a) {
  asm volatile("ldmatrix.sync.aligned.m8n8.x4.trans.shared.b16 {%0,%1,%2,%3}, [%4];"
               : "=r"(r[0]), "=r"(r[1]), "=r"(r[2]), "=r"(r[3]) : "r"(a));
}
__device__ __forceinline__ void mma16816(float* d, const uint32_t* a, const uint32_t* b) {
  asm volatile("mma.sync.aligned.m16n8k16.row.col.f32.f16.f16.f32 "
               "{%0,%1,%2,%3}, {%4,%5,%6,%7}, {%8,%9}, {%0,%1,%2,%3};"
               : "+f"(d[0]), "+f"(d[1]), "+f"(d[2]), "+f"(d[3])
               : "r"(a[0]), "r"(a[1]), "r"(a[2]), "r"(a[3]), "r"(b[0]), "r"(b[1]));
}
__device__ __forceinline__ uint32_t packh2(float lo, float hi) {
  uint32_t p;
  asm("cvt.rn.f16x2.f32 %0, %1, %2;" : "=r"(p) : "f"(hi), "f"(lo));
  return p;
}
__device__ __forceinline__ float ex2f(float x) {
  float r;
  asm("ex2.approx.f32 %0, %1;" : "=f"(r) : "f"(x));
  return r;
}

// ---------------------------------------------------------------------------
// merged prep kernel: convx (all blocks) + weight/bias convert + rpb*log2e
// ---------------------------------------------------------------------------
__global__ void prep_all_kernel(const float* __restrict__ x,
                                const float* __restrict__ qkvw,
                                const float* __restrict__ projw,
                                const float* __restrict__ qb,
                                const float* __restrict__ vb,
                                const float* __restrict__ table) {
  int g = blockIdx.x * 256 + threadIdx.x;

  // ---- convx: x [B,H*W,C] fp32 -> g_xh [win*196, C] fp16 (gather fused) ----
  {
    int m = g / 96, kk = g - m * 96;               // g < M_*96 always (grid sized)
    int w = m / N_, n = m - w * N_;
    int b = w >> 4, wr = w & 15, wh = wr >> 2, ww = wr & 3;
    int ii = n / WS_, jj = n - ii * WS_;
    size_t xr = (size_t)b * (HH * WWp) + (size_t)(wh * WS_ + ii) * WWp + (ww * WS_ + jj);
    const float4* src = (const float4*)(x + xr * C + kk * 8);
    float4 v0 = src[0], v1 = src[1];
    union { int4 i4; __half2 h2v[4]; } o;
    o.h2v[0] = __floats2half2_rn(v0.x, v0.y);
    o.h2v[1] = __floats2half2_rn(v0.z, v0.w);
    o.h2v[2] = __floats2half2_rn(v1.x, v1.y);
    o.h2v[3] = __floats2half2_rn(v1.z, v1.w);
    *(int4*)(g_xh + (size_t)m * C + kk * 8) = o.i4;
  }

  // ---- weight/bias conversion ----
  if (g < 2304 * 768) g_wqkv[g] = __float2half(qkvw[g]);
  if (g < 768 * 768)  g_wproj[g] = __float2half(projw[g]);
  if (g < 2304) g_bqkv[g] = (g < 768) ? qb[g] : ((g < 1536) ? 0.0f : vb[g - 1536]);

  // ---- rpb * log2e, TILE-PERMUTED cols: j = 8*nb+2*tig+e at p = 8*tig+2*nb+e
  if (g < N_ * RLD) {
    int a = g / RLD, b = g - a * RLD;
    int j = b & 31;
    int p = 8 * ((j >> 1) & 3) + 2 * (j >> 3) + (j & 1);
    int bp = (b & ~31) + p;
    if (b < N_) {
      int i1 = a / WS_, j1 = a - i1 * WS_;
      int i2 = b / WS_, j2 = b - i2 * WS_;
      int idx = (i1 - i2 + WS_ - 1) * (2 * WS_ - 1) + (j1 - j2 + WS_ - 1);
#pragma unroll
      for (int hh = 0; hh < NH_; hh++)
        g_rpbh[(size_t)hh * N_ * RLD + a * RLD + bp] =
            __float2half(table[idx * NH_ + hh] * L2E);
    } else {
#pragma unroll
      for (int hh = 0; hh < NH_; hh++)
        g_rpbh[(size_t)hh * N_ * RLD + a * RLD + bp] = __float2half(0.0f);
    }
  }
}

// ---------------------------------------------------------------------------
// WMMA GEMM (frozen winner): CTA 128 thr, tile 128x128, warp tile 64x64,
// BK=32, 3-stage cp.async, single barrier per k-iter, 2 CTAs/SM.
// MODE 0: q scale now 0.125*log2e (exp2 folding).
// ---------------------------------------------------------------------------
template <int MODE>
__global__ __launch_bounds__(128, 2) void gemm5_kernel(const float* __restrict__ bias_in,
                                                       float* __restrict__ out_f) {
  constexpr int BM = 128, BN = 128, S = 3;
  constexpr int LDA = 40, LDB = 40, LDE = 68;
  constexpr int NKT = KQ / 32;
  constexpr int ABYTES = BM * LDA * 2;
  constexpr int STG = ABYTES + BN * LDB * 2;

  extern __shared__ __align__(16) char dsm[];
  float* ep = (float*)dsm;

  const __half* __restrict__ A  = (MODE == 0) ? g_xh : g_ao;
  const __half* __restrict__ Bw = (MODE == 0) ? g_wqkv : g_wproj;
  const int n0 = blockIdx.x * BN;
  const int m0 = blockIdx.y * BM;
  const int tid = threadIdx.x;
  const int warp = tid >> 5;
  const int wm = warp >> 1, wn = warp & 1;

  wmma::fragment<wmma::accumulator, 16, 16, 16, float> acc[4][4];
#pragma unroll
  for (int i = 0; i < 4; i++)
#pragma unroll
    for (int j = 0; j < 4; j++) wmma::fill_fragment(acc[i][j], 0.0f);

  auto load_stage = [&](int kt) {
    const int slot = kt % S;
    char* abase = dsm + slot * STG;
    char* bbase = abase + ABYTES;
    const char* ag = (const char*)(A + (size_t)m0 * KQ + kt * 32);
    const char* bg = (const char*)(Bw + (size_t)n0 * KQ + kt * 32);
#pragma unroll
    for (int i = 0; i < 4; i++) {
      int q = tid + i * 128; int r = q >> 2, co = q & 3;
      cpa16(smem_u32(abase + r * (LDA * 2) + co * 16),
            ag + (size_t)r * (KQ * 2) + co * 16, true);
    }
#pragma unroll
    for (int i = 0; i < 4; i++) {
      int q = tid + i * 128; int r = q >> 2, co = q & 3;
      cpa16(smem_u32(bbase + r * (LDB * 2) + co * 16),
            bg + (size_t)r * (KQ * 2) + co * 16, true);
    }
    asm volatile("cp.async.commit_group;" ::: "memory");
  };

  load_stage(0);
  load_stage(1);

  for (int kt = 0; kt < NKT; kt++) {
    if (kt < NKT - 1) asm volatile("cp.async.wait_group 1;" ::: "memory");
    else              asm volatile("cp.async.wait_group 0;" ::: "memory");
    __syncthreads();
    if (kt + 2 < NKT) load_stage(kt + 2);

    const int slot = kt % S;
    const __half* sA = (const __half*)(dsm + slot * STG);
    const __half* sB = (const __half*)(dsm + slot * STG + ABYTES);
#pragma unroll
    for (int ks = 0; ks < 2; ks++) {
      wmma::fragment<wmma::matrix_a, 16, 16, 16, __half, wmma::row_major> af[4];
      wmma::fragment<wmma::matrix_b, 16, 16, 16, __half, wmma::col_major> bf[4];
#pragma unroll
      for (int i = 0; i < 4; i++)
        wmma::load_matrix_sync(af[i], &sA[(wm * 64 + i * 16) * LDA + ks * 16], LDA);
#pragma unroll
      for (int j = 0; j < 4; j++)
        wmma::load_matrix_sync(bf[j], &sB[(wn * 64 + j * 16) * LDB + ks * 16], LDB);
#pragma unroll
      for (int i = 0; i < 4; i++)
#pragma unroll
        for (int j = 0; j < 4; j++)
          wmma::mma_sync(acc[i][j], af[i], bf[j], acc[i][j]);
    }
  }

#pragma unroll 1
  for (int p = 0; p < 2; p++) {
    __syncthreads();
    if (wn == p) {
#pragma unroll
      for (int i = 0; i < 4; i++)
#pragma unroll
        for (int j = 0; j < 4; j++)
          wmma::store_matrix_sync(&ep[(wm * 64 + i * 16) * LDE + j * 16],
                                  acc[i][j], LDE, wmma::mem_row_major);
    }
    __syncthreads();
#pragma unroll 4
    for (int it = 0; it < 32; it++) {
      int idx = it * 128 + tid;
      int r = idx >> 5, ccp = idx & 31;
      int cc = ccp * 2;
      int m = m0 + r;
      int c = n0 + p * 64 + cc;
      float v0 = ep[r * LDE + cc];
      float v1 = ep[r * LDE + cc + 1];
      int w = m / N_, n = m - w * N_;
      if (MODE == 0) {
        v0 += g_bqkv[c];
        v1 += g_bqkv[c + 1];
        int sec = c / 768, cu = c - sec * 768;
        int h = cu >> 6, d = cu & 63;
        __half* dst = ((sec == 0) ? g_q : (sec == 1) ? g_k : g_v) +
                      ((size_t)(w * NH_ + h) * N_ + n) * HD + d;
        float sc = (sec == 0) ? (0.125f * L2E) : 1.0f;
        *(__half2*)dst = __floats2half2_rn(v0 * sc, v1 * sc);
      } else {
        v0 += bias_in[c];
        v1 += bias_in[c + 1];
        int b = w >> 4, wr = w & 15, wh = wr >> 2, ww = wr & 3;
        int ii = n / WS_, jj = n - ii * WS_;
        size_t xr = (size_t)b * (HH * WWp) + (size_t)(wh * WS_ + ii) * WWp + (ww * WS_ + jj);
        *(float2*)(out_f + xr * C + c) = make_float2(v0, v1);
      }
    }
  }
}

// ---------------------------------------------------------------------------
// attention v8: R12 structure + (a) bare ex2.approx (log2e pre-folded into
// q and rpb), (b) K fragments via paired ldmatrix.x4 (halved LDSM count).
// ---------------------------------------------------------------------------
__global__ __launch_bounds__(128) void attn_kernel() {
  constexpr int KT = 32, NT = 7;
  constexpr int LQB = 144;
  constexpr int KBYTES = KT * LQB;              // 4608
  constexpr int STGB = 2 * KBYTES;              // 9216 (K + V)
  constexpr int QOFF = 3 * STGB;                // 27648

  extern __shared__ __align__(16) char asm_[];
  const uint32_t smb = smem_u32(asm_);

  const int h = blockIdx.x, w = blockIdx.y, qc = blockIdx.z;
  const int tid = threadIdx.x, warp = tid >> 5, lane = tid & 31;
  const int tig = lane & 3, tq = lane >> 2;
  const int row0 = qc * 128;

  const size_t base = ((size_t)w * NH_ + h) * N_ * HD;
  const __half* Qg = g_q + base;
  const __half* Kg = g_k + base;
  const __half* Vg = g_v + base;
  const __half* Rg = g_rpbh + (size_t)h * N_ * RLD;

#pragma unroll
  for (int i = 0; i < 8; i++) {
    int idx = tid + i * 128;
    int r = idx >> 3, c = idx & 7;
    int n = row0 + r;
    cpa16(smb + QOFF + r * LQB + c * 16, Qg + (size_t)n * HD + c * 8, n < N_);
  }
  asm volatile("cp.async.commit_group;" ::: "memory");

  auto load_stage = [&](int t) {
    const uint32_t sb = smb + (t % 3) * STGB;
#pragma unroll
    for (int i = 0; i < 2; i++) {
      int idx = tid + i * 128;
      int r = idx >> 3, c = idx & 7;
      int jg = t * KT + r;
      cpa16(sb + r * LQB + c * 16, Kg + (size_t)jg * HD + c * 8, jg < N_);
      cpa16(sb + KBYTES + r * LQB + c * 16, Vg + (size_t)jg * HD + c * 8, jg < N_);
    }
    asm volatile("cp.async.commit_group;" ::: "memory");
  };

  load_stage(0);
  load_stage(1);

  asm volatile("cp.async.wait_group 2;" ::: "memory");
  __syncthreads();
  uint32_t qa[2][4][4];
#pragma unroll
  for (int g = 0; g < 2; g++)
#pragma unroll
    for (int kk = 0; kk < 4; kk++) {
      uint32_t addr = smb + QOFF + (warp * 32 + g * 16 + (lane & 15)) * LQB +
                      (kk * 16 + ((lane >> 4) << 3)) * 2;
      ldx4(qa[g][kk], addr);
    }

  float oacc[2][8][4];
#pragma unroll
  for (int g = 0; g < 2; g++)
#pragma unroll
    for (int d = 0; d < 8; d++)
#pragma unroll
      for (int i = 0; i < 4; i++) oacc[g][d][i] = 0.0f;
  float rsum[2][2] = {{0.0f, 0.0f}, {0.0f, 0.0f}};

  for (int t = 0; t < NT; t++) {
    if (t < NT - 1) asm volatile("cp.async.wait_group 1;" ::: "memory");
    else            asm volatile("cp.async.wait_group 0;" ::: "memory");
    __syncthreads();
    if (t + 2 < NT) load_stage(t + 2);

    const uint32_t sb = smb + (t % 3) * STGB;

    uint32_t rpre[2][2][4];
#pragma unroll
    for (int g = 0; g < 2; g++)
#pragma unroll
      for (int p2 = 0; p2 < 2; p2++) {
        int rr = row0 + warp * 32 + g * 16 + tq + p2 * 8;
        int4 rq = make_int4(0, 0, 0, 0);
        if (rr < N_)
          rq = *(const int4*)(Rg + (size_t)rr * RLD + t * KT + 8 * tig);
        rpre[g][p2][0] = (uint32_t)rq.x;
        rpre[g][p2][1] = (uint32_t)rq.y;
        rpre[g][p2][2] = (uint32_t)rq.z;
        rpre[g][p2][3] = (uint32_t)rq.w;
      }

    // ---- S = Q K^T, exp2, pack. K frags via paired ldmatrix.x4:
    //   rows nbp*16+(lane&15), col-offset ((lane>>4)<<3) ->
    //   m0=n[0:8)k[0:8) m1=n[8:16)k[0:8) m2=n[0:8)k[8:16) m3=n[8:16)k[8:16)
    //   nb even uses {m0,m2}; nb odd uses {m1,m3}.
    uint32_t pa[2][2][4];
#pragma unroll
    for (int nbp = 0; nbp < 2; nbp++) {
      float s[2][2][4];
#pragma unroll
      for (int g = 0; g < 2; g++)
#pragma unroll
        for (int hf = 0; hf < 2; hf++)
#pragma unroll
          for (int i = 0; i < 4; i++) s[g][hf][i] = 0.0f;
#pragma unroll
      for (int kk = 0; kk < 4; kk++) {
        uint32_t kf4[4];
        uint32_t ka = sb + (nbp * 16 + (lane & 15)) * LQB +
                      (kk * 16 + ((lane >> 4) << 3)) * 2;
        ldx4(kf4, ka);
        uint32_t bA[2] = {kf4[0], kf4[2]};
        uint32_t bB[2] = {kf4[1], kf4[3]};
        mma16816(s[0][0], qa[0][kk], bA);
        mma16816(s[0][1], qa[0][kk], bB);
        mma16816(s[1][0], qa[1][kk], bA);
        mma16816(s[1][1], qa[1][kk], bB);
      }
#pragma unroll
      for (int hf = 0; hf < 2; hf++) {
        const int nb = nbp * 2 + hf;
        const int j0 = t * KT + nb * 8 + 2 * tig;
        const bool jv = (j0 < N_);
#pragma unroll
        for (int g = 0; g < 2; g++) {
          const float* sg = s[g][hf];
          float e0 = 0, e1 = 0, e2 = 0, e3 = 0;
          if (jv) {
            float2 fl = __half22float2(*(const __half2*)&rpre[g][0][nb]);
            float2 fh = __half22float2(*(const __half2*)&rpre[g][1][nb]);
            e0 = ex2f(sg[0] + fl.x);
            e1 = ex2f(sg[1] + fl.y);
            e2 = ex2f(sg[2] + fh.x);
            e3 = ex2f(sg[3] + fh.y);
          }
          rsum[g][0] += e0 + e1;
          rsum[g][1] += e2 + e3;
          pa[g][nb >> 1][(nb & 1) * 2 + 0] = packh2(e0, e1);
          pa[g][nb >> 1][(nb & 1) * 2 + 1] = packh2(e2, e3);
        }
      }
    }

#pragma unroll
    for (int kb = 0; kb < 2; kb++)
#pragma unroll
      for (int dh = 0; dh < 4; dh++) {
        uint32_t vt[4];
        uint32_t va = sb + KBYTES + (kb * 16 + (lane & 15)) * LQB +
                      (dh * 16 + ((lane >> 4) << 3)) * 2;
        ldx4t(vt, va);
        mma16816(oacc[0][2 * dh],     pa[0][kb], vt + 0);
        mma16816(oacc[0][2 * dh + 1], pa[0][kb], vt + 2);
        mma16816(oacc[1][2 * dh],     pa[1][kb], vt + 0);
        mma16816(oacc[1][2 * dh + 1], pa[1][kb], vt + 2);
      }
  }

#pragma unroll
  for (int g = 0; g < 2; g++) {
    float slo = rsum[g][0];
    slo += __shfl_xor_sync(0xFFFFFFFFu, slo, 1);
    slo += __shfl_xor_sync(0xFFFFFFFFu, slo, 2);
    float shi = rsum[g][1];
    shi += __shfl_xor_sync(0xFFFFFFFFu, shi, 1);
    shi += __shfl_xor_sync(0xFFFFFFFFu, shi, 2);
    float ilo = 1.0f / slo, ihi = 1.0f / shi;
    int nlo = row0 + warp * 32 + g * 16 + tq;
    int nhi = nlo + 8;
    __half* rowlo = g_ao + ((size_t)w * N_ + nlo) * C + h * HD;
    __half* rowhi = g_ao + ((size_t)w * N_ + nhi) * C + h * HD;
#pragma unroll
    for (int db = 0; db < 8; db++) {
      int col = db * 8 + 2 * tig;
      if (nlo < N_)
        *(__half2*)(rowlo + col) =
            __floats2half2_rn(oacc[g][db][0] * ilo, oacc[g][db][1] * ilo);
      if (nhi < N_)
        *(__half2*)(rowhi + col) =
            __floats2half2_rn(oacc[g][db][2] * ihi, oacc[g][db][3] * ihi);
    }
  }
}

// ---------------------------------------------------------------------------
extern "C" void kernel_launch(void* const* d_in, const int* in_sizes, int n_in,
                              void* d_out, int out_size) {
  const float* x     = (const float*)d_in[0];
  const float* qkvw  = (const float*)d_in[1];
  const float* qb    = (const float*)d_in[2];
  const float* vb    = (const float*)d_in[3];
  const float* table = (const float*)d_in[4];
  const float* projw = (const float*)d_in[5];
  const float* projb = (const float*)d_in[6];
  float* out = (float*)d_out;
  (void)in_sizes; (void)n_in; (void)out_size;

  const int DSMEM_G = 3 * 20480;                     // 61440
  const int DSMEM_A = 3 * 9216 + 128 * 144;          // 46080
  cudaFuncSetAttribute(gemm5_kernel<0>, cudaFuncAttributeMaxDynamicSharedMemorySize, DSMEM_G);
  cudaFuncSetAttribute(gemm5_kernel<1>, cudaFuncAttributeMaxDynamicSharedMemorySize, DSMEM_G);
  cudaFuncSetAttribute(attn_kernel, cudaFuncAttributeMaxDynamicSharedMemorySize, DSMEM_A);

  prep_all_kernel<<<(M_ * 96) / 256, 256>>>(x, qkvw, projw, qb, vb, table);
  gemm5_kernel<0><<<dim3(2304 / 128, M_ / 128), 128, DSMEM_G>>>(nullptr, nullptr);
  attn_kernel<<<dim3(NH_, NWIN, 2), 128, DSMEM_A>>>();
  gemm5_kernel<1><<<dim3(768 / 128, M_ / 128), 128, DSMEM_G>>>(projb, out);
}

// round 16
// speedup vs baseline: 1.0707x; 1.0312x over previous
#include <cuda_runtime.h>
#include <cuda_fp16.h>
#include <mma.h>
#include <cstdint>

using namespace nvcuda;

// Problem constants (static shapes)
constexpr int HH   = 56;
constexpr int WWp  = 56;
constexpr int C    = 768;
constexpr int NH_  = 12;
constexpr int HD   = 64;
constexpr int WS_  = 14;
constexpr int N_   = 196;        // tokens per window
constexpr int NWIN = 256;        // 16 batch * 16 windows
constexpr int M_   = NWIN * N_;  // 50176 rows
constexpr int KQ   = 768;
constexpr int RLD  = 224;        // padded rpb row stride (halfs) = 7 tiles x 32
constexpr float L2E = 1.4426950408889634f;

// -------- device scratch (allocation-free rule: __device__ globals) --------
__device__ __half g_xh[(size_t)M_ * C];          // window-ordered fp16 x
__device__ __half g_wqkv[2304 * 768];
__device__ __half g_wproj[768 * 768];
__device__ float  g_bqkv[2304];
__device__ __half g_q[(size_t)NWIN * NH_ * N_ * HD];   // pre-scaled by 0.125*log2e
__device__ __half g_k[(size_t)NWIN * NH_ * N_ * HD];
__device__ __half g_v[(size_t)NWIN * NH_ * N_ * HD];
__device__ __half g_rpbh[(size_t)NH_ * N_ * RLD];  // half * log2e, tile-permuted cols
__device__ __half g_ao[(size_t)M_ * C];          // attention output (proj input)

// ---------------- raw-PTX helpers (all sm_80-level; safe on compute_103) ----
__device__ __forceinline__ uint32_t smem_u32(const void* p) {
  uint32_t a;
  asm("{ .reg .u64 t; cvta.to.shared.u64 t, %1; cvt.u32.u64 %0, t; }" : "=r"(a) : "l"(p));
  return a;
}
__device__ __forceinline__ void cpa16(uint32_t dst, const void* src, bool valid) {
  int sz = valid ? 16 : 0;
  asm volatile("cp.async.cg.shared.global [%0], [%1], 16, %2;"
               :: "r"(dst), "l"(src), "r"(sz) : "memory");
}
__device__ __forceinline__ void ldx4(uint32_t* r, uint32_t a) {
  asm volatile("ldmatrix.sync.aligned.m8n8.x4.shared.b16 {%0,%1,%2,%3}, [%4];"
               : "=r"(r[0]), "=r"(r[1]), "=r"(r[2]), "=r"(r[3]) : "r"(a));
}
__device__ __forceinline__ void ldx4t(uint32_t* r, uint32_t a) {
  asm volatile("ldmatrix.sync.aligned.m8n8.x4.trans.shared.b16 {%0,%1,%2,%3}, [%4];"
               : "=r"(r[0]), "=r"(r[1]), "=r"(r[2]), "=r"(r[3]) : "r"(a));
}
__device__ __forceinline__ void mma16816(float* d, const uint32_t* a, const uint32_t* b) {
  asm volatile("mma.sync.aligned.m16n8k16.row.col.f32.f16.f16.f32 "
               "{%0,%1,%2,%3}, {%4,%5,%6,%7}, {%8,%9}, {%0,%1,%2,%3};"
               : "+f"(d[0]), "+f"(d[1]), "+f"(d[2]), "+f"(d[3])
               : "r"(a[0]), "r"(a[1]), "r"(a[2]), "r"(a[3]), "r"(b[0]), "r"(b[1]));
}
__device__ __forceinline__ uint32_t packh2(float lo, float hi) {
  uint32_t p;
  asm("cvt.rn.f16x2.f32 %0, %1, %2;" : "=r"(p) : "f"(hi), "f"(lo));
  return p;
}
__device__ __forceinline__ float ex2f(float x) {
  float r;
  asm("ex2.approx.f32 %0, %1;" : "=f"(r) : "f"(x));
  return r;
}

// ---------------------------------------------------------------------------
// merged prep kernel: convx (all blocks) + weight/bias convert + rpb*log2e
// ---------------------------------------------------------------------------
__global__ void prep_all_kernel(const float* __restrict__ x,
                                const float* __restrict__ qkvw,
                                const float* __restrict__ projw,
                                const float* __restrict__ qb,
                                const float* __restrict__ vb,
                                const float* __restrict__ table) {
  int g = blockIdx.x * 256 + threadIdx.x;

  // ---- convx: x [B,H*W,C] fp32 -> g_xh [win*196, C] fp16 (gather fused) ----
  {
    int m = g / 96, kk = g - m * 96;               // g < M_*96 always (grid sized)
    int w = m / N_, n = m - w * N_;
    int b = w >> 4, wr = w & 15, wh = wr >> 2, ww = wr & 3;
    int ii = n / WS_, jj = n - ii * WS_;
    size_t xr = (size_t)b * (HH * WWp) + (size_t)(wh * WS_ + ii) * WWp + (ww * WS_ + jj);
    const float4* src = (const float4*)(x + xr * C + kk * 8);
    float4 v0 = src[0], v1 = src[1];
    union { int4 i4; __half2 h2v[4]; } o;
    o.h2v[0] = __floats2half2_rn(v0.x, v0.y);
    o.h2v[1] = __floats2half2_rn(v0.z, v0.w);
    o.h2v[2] = __floats2half2_rn(v1.x, v1.y);
    o.h2v[3] = __floats2half2_rn(v1.z, v1.w);
    *(int4*)(g_xh + (size_t)m * C + kk * 8) = o.i4;
  }

  // ---- weight/bias conversion ----
  if (g < 2304 * 768) g_wqkv[g] = __float2half(qkvw[g]);
  if (g < 768 * 768)  g_wproj[g] = __float2half(projw[g]);
  if (g < 2304) g_bqkv[g] = (g < 768) ? qb[g] : ((g < 1536) ? 0.0f : vb[g - 1536]);

  // ---- rpb * log2e, TILE-PERMUTED cols: j = 8*nb+2*tig+e at p = 8*tig+2*nb+e
  if (g < N_ * RLD) {
    int a = g / RLD, b = g - a * RLD;
    int j = b & 31;
    int p = 8 * ((j >> 1) & 3) + 2 * (j >> 3) + (j & 1);
    int bp = (b & ~31) + p;
    if (b < N_) {
      int i1 = a / WS_, j1 = a - i1 * WS_;
      int i2 = b / WS_, j2 = b - i2 * WS_;
      int idx = (i1 - i2 + WS_ - 1) * (2 * WS_ - 1) + (j1 - j2 + WS_ - 1);
#pragma unroll
      for (int hh = 0; hh < NH_; hh++)
        g_rpbh[(size_t)hh * N_ * RLD + a * RLD + bp] =
            __float2half(table[idx * NH_ + hh] * L2E);
    } else {
#pragma unroll
      for (int hh = 0; hh < NH_; hh++)
        g_rpbh[(size_t)hh * N_ * RLD + a * RLD + bp] = __float2half(0.0f);
    }
  }
}

// ---------------------------------------------------------------------------
// WMMA GEMM (frozen mainloop) + QUAD-VECTORIZED epilogue: per iter a thread
// handles 4 consecutive columns -> one float4 smem read, one float4 bias
// load, one store (uint2 of 4 halfs for QKV / float4 for proj), and the
// m/N_ + window-coordinate computation once per quad instead of per pair.
// ---------------------------------------------------------------------------
template <int MODE>
__global__ __launch_bounds__(128, 2) void gemm5_kernel(const float* __restrict__ bias_in,
                                                       float* __restrict__ out_f) {
  constexpr int BM = 128, BN = 128, S = 3;
  constexpr int LDA = 40, LDB = 40, LDE = 68;
  constexpr int NKT = KQ / 32;
  constexpr int ABYTES = BM * LDA * 2;
  constexpr int STG = ABYTES + BN * LDB * 2;

  extern __shared__ __align__(16) char dsm[];
  float* ep = (float*)dsm;

  const __half* __restrict__ A  = (MODE == 0) ? g_xh : g_ao;
  const __half* __restrict__ Bw = (MODE == 0) ? g_wqkv : g_wproj;
  const int n0 = blockIdx.x * BN;
  const int m0 = blockIdx.y * BM;
  const int tid = threadIdx.x;
  const int warp = tid >> 5;
  const int wm = warp >> 1, wn = warp & 1;

  wmma::fragment<wmma::accumulator, 16, 16, 16, float> acc[4][4];
#pragma unroll
  for (int i = 0; i < 4; i++)
#pragma unroll
    for (int j = 0; j < 4; j++) wmma::fill_fragment(acc[i][j], 0.0f);

  auto load_stage = [&](int kt) {
    const int slot = kt % S;
    char* abase = dsm + slot * STG;
    char* bbase = abase + ABYTES;
    const char* ag = (const char*)(A + (size_t)m0 * KQ + kt * 32);
    const char* bg = (const char*)(Bw + (size_t)n0 * KQ + kt * 32);
#pragma unroll
    for (int i = 0; i < 4; i++) {
      int q = tid + i * 128; int r = q >> 2, co = q & 3;
      cpa16(smem_u32(abase + r * (LDA * 2) + co * 16),
            ag + (size_t)r * (KQ * 2) + co * 16, true);
    }
#pragma unroll
    for (int i = 0; i < 4; i++) {
      int q = tid + i * 128; int r = q >> 2, co = q & 3;
      cpa16(smem_u32(bbase + r * (LDB * 2) + co * 16),
            bg + (size_t)r * (KQ * 2) + co * 16, true);
    }
    asm volatile("cp.async.commit_group;" ::: "memory");
  };

  load_stage(0);
  load_stage(1);

  for (int kt = 0; kt < NKT; kt++) {
    if (kt < NKT - 1) asm volatile("cp.async.wait_group 1;" ::: "memory");
    else              asm volatile("cp.async.wait_group 0;" ::: "memory");
    __syncthreads();
    if (kt + 2 < NKT) load_stage(kt + 2);

    const int slot = kt % S;
    const __half* sA = (const __half*)(dsm + slot * STG);
    const __half* sB = (const __half*)(dsm + slot * STG + ABYTES);
#pragma unroll
    for (int ks = 0; ks < 2; ks++) {
      wmma::fragment<wmma::matrix_a, 16, 16, 16, __half, wmma::row_major> af[4];
      wmma::fragment<wmma::matrix_b, 16, 16, 16, __half, wmma::col_major> bf[4];
#pragma unroll
      for (int i = 0; i < 4; i++)
        wmma::load_matrix_sync(af[i], &sA[(wm * 64 + i * 16) * LDA + ks * 16], LDA);
#pragma unroll
      for (int j = 0; j < 4; j++)
        wmma::load_matrix_sync(bf[j], &sB[(wn * 64 + j * 16) * LDB + ks * 16], LDB);
#pragma unroll
      for (int i = 0; i < 4; i++)
#pragma unroll
        for (int j = 0; j < 4; j++)
          wmma::mma_sync(acc[i][j], af[i], bf[j], acc[i][j]);
    }
  }

#pragma unroll 1
  for (int p = 0; p < 2; p++) {
    __syncthreads();
    if (wn == p) {
#pragma unroll
      for (int i = 0; i < 4; i++)
#pragma unroll
        for (int j = 0; j < 4; j++)
          wmma::store_matrix_sync(&ep[(wm * 64 + i * 16) * LDE + j * 16],
                                  acc[i][j], LDE, wmma::mem_row_major);
    }
    __syncthreads();
    // quad epilogue: 128 rows x 16 quads = 2048 per phase, 16 iters
#pragma unroll 4
    for (int it = 0; it < 16; it++) {
      int idx = it * 128 + tid;
      int r = idx >> 4, qq = idx & 15;
      int cc = qq * 4;
      int m = m0 + r;
      int c = n0 + p * 64 + cc;
      float4 v = *(const float4*)&ep[r * LDE + cc];
      int w = m / N_, n = m - w * N_;
      if (MODE == 0) {
        const float4 bq = *(const float4*)&g_bqkv[c];
        int sec = c / 768, cu = c - sec * 768;
        int h = cu >> 6, d = cu & 63;                // quad stays within one head
        __half* dst = ((sec == 0) ? g_q : (sec == 1) ? g_k : g_v) +
                      ((size_t)(w * NH_ + h) * N_ + n) * HD + d;
        float sc = (sec == 0) ? (0.125f * L2E) : 1.0f;
        uint2 o;
        o.x = packh2((v.x + bq.x) * sc, (v.y + bq.y) * sc);
        o.y = packh2((v.z + bq.z) * sc, (v.w + bq.w) * sc);
        *(uint2*)dst = o;
      } else {
        const float4 bb = *(const float4*)&bias_in[c];
        v.x += bb.x; v.y += bb.y; v.z += bb.z; v.w += bb.w;
        int b = w >> 4, wr = w & 15, wh = wr >> 2, ww = wr & 3;
        int ii = n / WS_, jj = n - ii * WS_;
        size_t xr = (size_t)b * (HH * WWp) + (size_t)(wh * WS_ + ii) * WWp + (ww * WS_ + jj);
        *(float4*)(out_f + xr * C + c) = v;
      }
    }
  }
}

// ---------------------------------------------------------------------------
// attention v8 (R15 winner, verbatim): 128-thread CTAs, 2 q-blocks per (w,h),
// register-resident flash chain, ex2.approx with pre-folded log2e, paired
// ldmatrix.x4 K fragments, vectorized tile-permuted rpb prefetch.
// ---------------------------------------------------------------------------
__global__ __launch_bounds__(128) void attn_kernel() {
  constexpr int KT = 32, NT = 7;
  constexpr int LQB = 144;
  constexpr int KBYTES = KT * LQB;              // 4608
  constexpr int STGB = 2 * KBYTES;              // 9216 (K + V)
  constexpr int QOFF = 3 * STGB;                // 27648

  extern __shared__ __align__(16) char asm_[];
  const uint32_t smb = smem_u32(asm_);

  const int h = blockIdx.x, w = blockIdx.y, qc = blockIdx.z;
  const int tid = threadIdx.x, warp = tid >> 5, lane = tid & 31;
  const int tig = lane & 3, tq = lane >> 2;
  const int row0 = qc * 128;

  const size_t base = ((size_t)w * NH_ + h) * N_ * HD;
  const __half* Qg = g_q + base;
  const __half* Kg = g_k + base;
  const __half* Vg = g_v + base;
  const __half* Rg = g_rpbh + (size_t)h * N_ * RLD;

#pragma unroll
  for (int i = 0; i < 8; i++) {
    int idx = tid + i * 128;
    int r = idx >> 3, c = idx & 7;
    int n = row0 + r;
    cpa16(smb + QOFF + r * LQB + c * 16, Qg + (size_t)n * HD + c * 8, n < N_);
  }
  asm volatile("cp.async.commit_group;" ::: "memory");

  auto load_stage = [&](int t) {
    const uint32_t sb = smb + (t % 3) * STGB;
#pragma unroll
    for (int i = 0; i < 2; i++) {
      int idx = tid + i * 128;
      int r = idx >> 3, c = idx & 7;
      int jg = t * KT + r;
      cpa16(sb + r * LQB + c * 16, Kg + (size_t)jg * HD + c * 8, jg < N_);
      cpa16(sb + KBYTES + r * LQB + c * 16, Vg + (size_t)jg * HD + c * 8, jg < N_);
    }
    asm volatile("cp.async.commit_group;" ::: "memory");
  };

  load_stage(0);
  load_stage(1);

  asm volatile("cp.async.wait_group 2;" ::: "memory");
  __syncthreads();
  uint32_t qa[2][4][4];
#pragma unroll
  for (int g = 0; g < 2; g++)
#pragma unroll
    for (int kk = 0; kk < 4; kk++) {
      uint32_t addr = smb + QOFF + (warp * 32 + g * 16 + (lane & 15)) * LQB +
                      (kk * 16 + ((lane >> 4) << 3)) * 2;
      ldx4(qa[g][kk], addr);
    }

  float oacc[2][8][4];
#pragma unroll
  for (int g = 0; g < 2; g++)
#pragma unroll
    for (int d = 0; d < 8; d++)
#pragma unroll
      for (int i = 0; i < 4; i++) oacc[g][d][i] = 0.0f;
  float rsum[2][2] = {{0.0f, 0.0f}, {0.0f, 0.0f}};

  for (int t = 0; t < NT; t++) {
    if (t < NT - 1) asm volatile("cp.async.wait_group 1;" ::: "memory");
    else            asm volatile("cp.async.wait_group 0;" ::: "memory");
    __syncthreads();
    if (t + 2 < NT) load_stage(t + 2);

    const uint32_t sb = smb + (t % 3) * STGB;

    uint32_t rpre[2][2][4];
#pragma unroll
    for (int g = 0; g < 2; g++)
#pragma unroll
      for (int p2 = 0; p2 < 2; p2++) {
        int rr = row0 + warp * 32 + g * 16 + tq + p2 * 8;
        int4 rq = make_int4(0, 0, 0, 0);
        if (rr < N_)
          rq = *(const int4*)(Rg + (size_t)rr * RLD + t * KT + 8 * tig);
        rpre[g][p2][0] = (uint32_t)rq.x;
        rpre[g][p2][1] = (uint32_t)rq.y;
        rpre[g][p2][2] = (uint32_t)rq.z;
        rpre[g][p2][3] = (uint32_t)rq.w;
      }

    uint32_t pa[2][2][4];
#pragma unroll
    for (int nbp = 0; nbp < 2; nbp++) {
      float s[2][2][4];
#pragma unroll
      for (int g = 0; g < 2; g++)
#pragma unroll
        for (int hf = 0; hf < 2; hf++)
#pragma unroll
          for (int i = 0; i < 4; i++) s[g][hf][i] = 0.0f;
#pragma unroll
      for (int kk = 0; kk < 4; kk++) {
        uint32_t kf4[4];
        uint32_t ka = sb + (nbp * 16 + (lane & 15)) * LQB +
                      (kk * 16 + ((lane >> 4) << 3)) * 2;
        ldx4(kf4, ka);
        uint32_t bA[2] = {kf4[0], kf4[2]};
        uint32_t bB[2] = {kf4[1], kf4[3]};
        mma16816(s[0][0], qa[0][kk], bA);
        mma16816(s[0][1], qa[0][kk], bB);
        mma16816(s[1][0], qa[1][kk], bA);
        mma16816(s[1][1], qa[1][kk], bB);
      }
#pragma unroll
      for (int hf = 0; hf < 2; hf++) {
        const int nb = nbp * 2 + hf;
        const int j0 = t * KT + nb * 8 + 2 * tig;
        const bool jv = (j0 < N_);
#pragma unroll
        for (int g = 0; g < 2; g++) {
          const float* sg = s[g][hf];
          float e0 = 0, e1 = 0, e2 = 0, e3 = 0;
          if (jv) {
            float2 fl = __half22float2(*(const __half2*)&rpre[g][0][nb]);
            float2 fh = __half22float2(*(const __half2*)&rpre[g][1][nb]);
            e0 = ex2f(sg[0] + fl.x);
            e1 = ex2f(sg[1] + fl.y);
            e2 = ex2f(sg[2] + fh.x);
            e3 = ex2f(sg[3] + fh.y);
          }
          rsum[g][0] += e0 + e1;
          rsum[g][1] += e2 + e3;
          pa[g][nb >> 1][(nb & 1) * 2 + 0] = packh2(e0, e1);
          pa[g][nb >> 1][(nb & 1) * 2 + 1] = packh2(e2, e3);
        }
      }
    }

#pragma unroll
    for (int kb = 0; kb < 2; kb++)
#pragma unroll
      for (int dh = 0; dh < 4; dh++) {
        uint32_t vt[4];
        uint32_t va = sb + KBYTES + (kb * 16 + (lane & 15)) * LQB +
                      (dh * 16 + ((lane >> 4) << 3)) * 2;
        ldx4t(vt, va);
        mma16816(oacc[0][2 * dh],     pa[0][kb], vt + 0);
        mma16816(oacc[0][2 * dh + 1], pa[0][kb], vt + 2);
        mma16816(oacc[1][2 * dh],     pa[1][kb], vt + 0);
        mma16816(oacc[1][2 * dh + 1], pa[1][kb], vt + 2);
      }
  }

#pragma unroll
  for (int g = 0; g < 2; g++) {
    float slo = rsum[g][0];
    slo += __shfl_xor_sync(0xFFFFFFFFu, slo, 1);
    slo += __shfl_xor_sync(0xFFFFFFFFu, slo, 2);
    float shi = rsum[g][1];
    shi += __shfl_xor_sync(0xFFFFFFFFu, shi, 1);
    shi += __shfl_xor_sync(0xFFFFFFFFu, shi, 2);
    float ilo = 1.0f / slo, ihi = 1.0f / shi;
    int nlo = row0 + warp * 32 + g * 16 + tq;
    int nhi = nlo + 8;
    __half* rowlo = g_ao + ((size_t)w * N_ + nlo) * C + h * HD;
    __half* rowhi = g_ao + ((size_t)w * N_ + nhi) * C + h * HD;
#pragma unroll
    for (int db = 0; db < 8; db++) {
      int col = db * 8 + 2 * tig;
      if (nlo < N_)
        *(__half2*)(rowlo + col) =
            __floats2half2_rn(oacc[g][db][0] * ilo, oacc[g][db][1] * ilo);
      if (nhi < N_)
        *(__half2*)(rowhi + col) =
            __floats2half2_rn(oacc[g][db][2] * ihi, oacc[g][db][3] * ihi);
    }
  }
}

// ---------------------------------------------------------------------------
extern "C" void kernel_launch(void* const* d_in, const int* in_sizes, int n_in,
                              void* d_out, int out_size) {
  const float* x     = (const float*)d_in[0];
  const float* qkvw  = (const float*)d_in[1];
  const float* qb    = (const float*)d_in[2];
  const float* vb    = (const float*)d_in[3];
  const float* table = (const float*)d_in[4];
  const float* projw = (const float*)d_in[5];
  const float* projb = (const float*)d_in[6];
  float* out = (float*)d_out;
  (void)in_sizes; (void)n_in; (void)out_size;

  const int DSMEM_G = 3 * 20480;                     // 61440
  const int DSMEM_A = 3 * 9216 + 128 * 144;          // 46080
  cudaFuncSetAttribute(gemm5_kernel<0>, cudaFuncAttributeMaxDynamicSharedMemorySize, DSMEM_G);
  cudaFuncSetAttribute(gemm5_kernel<1>, cudaFuncAttributeMaxDynamicSharedMemorySize, DSMEM_G);
  cudaFuncSetAttribute(attn_kernel, cudaFuncAttributeMaxDynamicSharedMemorySize, DSMEM_A);

  prep_all_kernel<<<(M_ * 96) / 256, 256>>>(x, qkvw, projw, qb, vb, table);
  gemm5_kernel<0><<<dim3(2304 / 128, M_ / 128), 128, DSMEM_G>>>(nullptr, nullptr);
  attn_kernel<<<dim3(NH_, NWIN, 2), 128, DSMEM_A>>>();
  gemm5_kernel<1><<<dim3(768 / 128, M_ / 128), 128, DSMEM_G>>>(projb, out);
}